// round 17
// baseline (speedup 1.0000x reference)
#include <cuda_runtime.h>
#include <cuda_fp16.h>
#include <cuda.h>

#define BB 4
#define NROWS 4096
#define MROWS 4096
#define CDIM 512
#define TOTQ (BB*NROWS)

// ---------------------------------------------------------------------------
// Device scratch
// ---------------------------------------------------------------------------
__device__ __align__(16) float g_rowsum[TOTQ];                 // 64 KB
__device__ __align__(16) __half g_inh[(size_t)2*TOTQ*CDIM];    // x | support
__device__ __align__(16) __half g_inl[(size_t)2*TOTQ*CDIM];
__device__ __align__(16) __half g_wvh[CDIM*CDIM];
__device__ __align__(16) __half g_wph[CDIM*CDIM];
__device__ __align__(16) __half g_qkh[(size_t)2*TOTQ*CDIM];    // q | k
__device__ __align__(16) __half g_qkl[(size_t)2*TOTQ*CDIM];
__device__ __align__(16) __half g_kth[(size_t)TOTQ*CDIM];
__device__ __align__(16) __half g_ah[(size_t)BB*NROWS*MROWS];  // scaled exp (hi), masked
__device__ __align__(16) __half g_o2h[(size_t)TOTQ*CDIM], g_o2l[(size_t)TOTQ*CDIM];

// ---------------------------------------------------------------------------
// device helpers
// ---------------------------------------------------------------------------
static __device__ __forceinline__ unsigned smem_u32(const void* p) {
    unsigned a;
    asm("{ .reg .u64 t; cvta.to.shared.u64 t, %1; cvt.u32.u64 %0, t; }" : "=r"(a) : "l"(p));
    return a;
}
static __device__ __forceinline__ void ldm_x4(unsigned& r0, unsigned& r1,
                                              unsigned& r2, unsigned& r3, unsigned a) {
    asm volatile("ldmatrix.sync.aligned.m8n8.x4.shared.b16 {%0,%1,%2,%3}, [%4];"
                 : "=r"(r0), "=r"(r1), "=r"(r2), "=r"(r3) : "r"(a));
}
static __device__ __forceinline__ void mma16816(float* c, const unsigned* a,
                                                const unsigned* b) {
    asm volatile(
        "mma.sync.aligned.m16n8k16.row.col.f32.f16.f16.f32 "
        "{%0,%1,%2,%3}, {%4,%5,%6,%7}, {%8,%9}, {%0,%1,%2,%3};"
        : "+f"(c[0]), "+f"(c[1]), "+f"(c[2]), "+f"(c[3])
        : "r"(a[0]), "r"(a[1]), "r"(a[2]), "r"(a[3]), "r"(b[0]), "r"(b[1]));
}
static __device__ __forceinline__ unsigned hpack(float a, float b) {
    __half2 t = __floats2half2_rn(a, b);
    return *reinterpret_cast<unsigned*>(&t);
}
static __device__ __forceinline__ unsigned hsplitpack(float v) {
    __half h = __float2half(v);
    float lo = v - __half2float(h);
    __half l = __float2half(lo);
    return (unsigned)(*reinterpret_cast<unsigned short*>(&h))
         | ((unsigned)(*reinterpret_cast<unsigned short*>(&l)) << 16);
}
static __device__ __forceinline__ void mbar_wait(unsigned mbar, unsigned phase) {
    asm volatile(
        "{\n\t.reg .pred P1;\n\t"
        "LAB_WAIT_%=:\n\t"
        "mbarrier.try_wait.parity.acquire.cta.shared::cta.b64 P1, [%0], %1, 0x989680;\n\t"
        "@P1 bra.uni LAB_DONE_%=;\n\t"
        "bra.uni LAB_WAIT_%=;\n\t"
        "LAB_DONE_%=:\n\t}"
        :: "r"(mbar), "r"(phase) : "memory");
}
static __device__ __forceinline__ void tma3(unsigned dst, const CUtensorMap* m,
                                            int x, int y, int z, unsigned mb) {
    asm volatile(
        "cp.async.bulk.tensor.3d.shared::cluster.global.tile.mbarrier::complete_tx::bytes "
        "[%0], [%1, {%2, %3, %4}], [%5];"
        :: "r"(dst), "l"(m), "r"(x), "r"(y), "r"(z), "r"(mb) : "memory");
}

// ---------------------------------------------------------------------------
// Split-fp16 HMMA GEMM, TMA loads. CTA 128 x TN, K-slab 64, NSTG-stage buffer.
// C = A @ B^T; A,B [rows,K] row-major.
// NTERMS=3: ah*bh+al*bh+ah*bl ; 2: ah*bh+al*bh ; 1: ah*bh
// MODE 1: Cf = acc + bias
// MODE 5: E = exp2(scale*acc)*2^-21 clamped (log2e folded into scale);
//         Ch = fp16(E)*mask;  rowsum(Cf) += E (pre-mask, atomic)
// MODE 6: bug-faithful permuted split write of acc/rowsum(bias) into (Ch,Cl)
// MODE 7: projection: Ch=hi(acc) always; q-tiles (m0<sC) also Cl=lo(acc);
//         k-tiles (m0>=sC) also write transposed hi into kth (=Cf cast)
// ---------------------------------------------------------------------------
#define TILEA 16384                 // 128x64 fp16

template<int MODE, int NTERMS, int TN, int MINB, int NSTG>
__global__ void __launch_bounds__(256, MINB) tma_gemm(
    const __grid_constant__ CUtensorMap mAh, const __grid_constant__ CUtensorMap mAl,
    const __grid_constant__ CUtensorMap mBh, const __grid_constant__ CUtensorMap mBl,
    int ldC, int Kdim, float scale, long long sC,
    const float* __restrict__ bias, const int* __restrict__ maskp,
    float* __restrict__ Cf,
    __half* __restrict__ Ch, __half* __restrict__ Cl)
{
    constexpr unsigned TILEBN = TN * 64 * 2;
    constexpr unsigned NA = (NTERMS >= 2) ? 2u : 1u;
    constexpr unsigned NB = (NTERMS == 3) ? 2u : 1u;
    constexpr unsigned OFF_BH = NA * TILEA;
    constexpr unsigned STGX = NA * TILEA + NB * TILEBN;
    constexpr int NBP = TN / 64;
    constexpr int NBW = TN / 32;

    extern __shared__ char smem[];
    __shared__ __align__(16) unsigned long long mbar[3];
    const unsigned sa = (smem_u32(smem) + 1023) & ~1023u;
    const unsigned mbq = smem_u32(mbar);
    const int tid = threadIdx.x;
    const int wid = tid >> 5;
    const int lane = tid & 31;
    const int m0 = blockIdx.y * 128;
    const int n0 = blockIdx.x * TN;
    const int bz = blockIdx.z;

    const int m_w = (wid >> 2) * 64;
    const int n_w = (wid & 3) * (TN / 4);

    if (tid == 0) {
#pragma unroll
        for (int i = 0; i < NSTG; i++)
            asm volatile("mbarrier.init.shared.b64 [%0], 1;"
                         :: "r"(mbq + i * 8) : "memory");
    }
    __syncthreads();

    const int nslab = Kdim / 64;
    auto issue = [&](int buf, int k0) {
        if (tid == 0) {
            const unsigned mb = mbq + buf * 8;
            asm volatile("mbarrier.arrive.expect_tx.shared.b64 _, [%0], %1;"
                         :: "r"(mb), "r"(STGX) : "memory");
            const unsigned base = sa + buf * STGX;
            tma3(base, &mAh, k0, m0, bz, mb);
            if (NTERMS >= 2) tma3(base + TILEA, &mAl, k0, m0, bz, mb);
            tma3(base + OFF_BH, &mBh, k0, n0, bz, mb);
            if (NTERMS == 3) tma3(base + OFF_BH + TILEBN, &mBl, k0, n0, bz, mb);
        }
    };

#pragma unroll
    for (int i = 0; i < NSTG; i++)
        if (i < nslab) issue(i, i * 64);

    float acc[4][NBW][4];
#pragma unroll
    for (int i = 0; i < 4; i++)
#pragma unroll
        for (int j = 0; j < NBW; j++)
#pragma unroll
            for (int p = 0; p < 4; p++) acc[i][j][p] = 0.f;

    const unsigned aoffL = (unsigned)(m_w + (lane & 15)) * 128 + ((lane >> 4) * 16);
    const unsigned boffL = (unsigned)(n_w + (lane & 7) + ((lane >> 4) << 3)) * 128
                         + ((lane & 8) ? 16 : 0);
    const unsigned sxor = (unsigned)(lane & 7) << 4;

    int phase[3] = {0, 0, 0};
    for (int s = 0; s < nslab; s++) {
        const int buf = s % NSTG;
        mbar_wait(mbq + buf * 8, (unsigned)phase[buf]);
        phase[buf] ^= 1;
        const unsigned st = sa + buf * STGX;
#pragma unroll
        for (int kk = 0; kk < 4; kk++) {
            unsigned ah[4][4], al[4][4];
#pragma unroll
            for (int mb = 0; mb < 4; mb++) {
                const unsigned a = st + ((aoffL + mb * 2048 + kk * 32) ^ sxor);
                ldm_x4(ah[mb][0], ah[mb][1], ah[mb][2], ah[mb][3], a);
                if (NTERMS >= 2)
                    ldm_x4(al[mb][0], al[mb][1], al[mb][2], al[mb][3], a + TILEA);
            }
#pragma unroll
            for (int nbp = 0; nbp < NBP; nbp++) {
                unsigned bh[2][2], bl[2][2];
                const unsigned b = st + OFF_BH + ((boffL + nbp * 2048 + kk * 32) ^ sxor);
                ldm_x4(bh[0][0], bh[0][1], bh[1][0], bh[1][1], b);
                if (NTERMS == 3)
                    ldm_x4(bl[0][0], bl[0][1], bl[1][0], bl[1][1], b + TILEBN);
#pragma unroll
                for (int mb = 0; mb < 4; mb++)
#pragma unroll
                    for (int j = 0; j < 2; j++) {
                        float* c = acc[mb][2 * nbp + j];
                        mma16816(c, ah[mb], bh[j]);
                        if (NTERMS >= 2) mma16816(c, al[mb], bh[j]);
                        if (NTERMS == 3) mma16816(c, ah[mb], bl[j]);
                    }
            }
        }
        __syncthreads();
        if (s + NSTG < nslab) issue(buf, (s + NSTG) * 64);
    }

    // ======================= epilogues =======================
    if (MODE == 1) {
#pragma unroll
        for (int mb = 0; mb < 4; mb++)
#pragma unroll
            for (int p = 0; p < 2; p++) {
                const long long row = m0 + m_w + mb * 16 + (lane >> 2) + p * 8;
#pragma unroll
                for (int nb = 0; nb < NBW; nb++) {
                    const int col = n0 + n_w + nb * 8 + (lane & 3) * 2;
                    float2 o = make_float2(acc[mb][nb][2 * p] + bias[col],
                                           acc[mb][nb][2 * p + 1] + bias[col + 1]);
                    *(float2*)&Cf[row * ldC + col] = o;
                }
            }
    }

    if (MODE == 7) {
        const bool is_k = (m0 >= (int)sC);
#pragma unroll
        for (int mb = 0; mb < 4; mb++)
#pragma unroll
            for (int p = 0; p < 2; p++) {
                const long long row = m0 + m_w + mb * 16 + (lane >> 2) + p * 8;
#pragma unroll
                for (int nb = 0; nb < NBW; nb++) {
                    const int col = n0 + n_w + nb * 8 + (lane & 3) * 2;
                    float v0 = acc[mb][nb][2 * p];
                    float v1 = acc[mb][nb][2 * p + 1];
                    __half h0 = __float2half(v0);
                    __half h1 = __float2half(v1);
                    *(unsigned*)&Ch[row * (long long)ldC + col] =
                        hpack(__half2float(h0), __half2float(h1));
                    if (!is_k)
                        *(unsigned*)&Cl[row * (long long)ldC + col] =
                            hpack(v0 - __half2float(h0), v1 - __half2float(h1));
                }
            }
        if (is_k) {
            // transpose hi tile into kth[b][d][m] (coalesced 256B rows)
            char* smal = smem + (int)(sa - smem_u32(smem));
            unsigned* S = (unsigned*)smal;
#pragma unroll
            for (int mb = 0; mb < 4; mb++)
#pragma unroll
                for (int p = 0; p < 2; p++) {
                    const int jl = m_w + mb * 16 + (lane >> 2) + p * 8;
#pragma unroll
                    for (int nb = 0; nb < NBW; nb++) {
                        const int cl = n_w + nb * 8 + (lane & 3) * 2;
                        __half h0 = __float2half(acc[mb][nb][2 * p]);
                        __half h1 = __float2half(acc[mb][nb][2 * p + 1]);
                        S[cl * 132 + jl] = (unsigned)*(unsigned short*)&h0;
                        S[(cl + 1) * 132 + jl] = (unsigned)*(unsigned short*)&h1;
                    }
                }
            __syncthreads();
            const int b = (int)((m0 - (int)sC) >> 12);
            const int mloc = m0 & 4095;
            __half* kt = (__half*)Cf;
            const long long kb = (long long)b * CDIM * MROWS + mloc;
#pragma unroll 4
            for (int dl = wid; dl < TN; dl += 8) {
                uint4 q = *(uint4*)&S[dl * 132 + 4 * lane];
                unsigned a0 = (q.x & 0xFFFFu) | (q.y << 16);
                unsigned a1 = (q.z & 0xFFFFu) | (q.w << 16);
                *(uint2*)(kt + kb + (long long)(n0 + dl) * MROWS + 4 * lane) =
                    make_uint2(a0, a1);
            }
        }
    }

    if (MODE == 5) {
        const float SC = 4.76837158203125e-7f;   // 2^-21
        float mk0[NBW], mk1[NBW];
#pragma unroll
        for (int nb = 0; nb < NBW; nb++) {
            const int col = n0 + n_w + nb * 8 + (lane & 3) * 2;
            int2 mk = *(const int2*)&maskp[col];
            mk0[nb] = (mk.x != 0) ? 1.f : 0.f;
            mk1[nb] = (mk.y != 0) ? 1.f : 0.f;
        }
        float rs[4][2];
#pragma unroll
        for (int mb = 0; mb < 4; mb++)
#pragma unroll
            for (int p = 0; p < 2; p++) rs[mb][p] = 0.f;
#pragma unroll
        for (int mb = 0; mb < 4; mb++)
#pragma unroll
            for (int nb = 0; nb < NBW; nb++)
#pragma unroll
                for (int p = 0; p < 2; p++) {
                    float e0 = fminf(exp2f(acc[mb][nb][2 * p] * scale) * SC, 60000.f);
                    float e1 = fminf(exp2f(acc[mb][nb][2 * p + 1] * scale) * SC, 60000.f);
                    acc[mb][nb][2 * p] = e0;
                    acc[mb][nb][2 * p + 1] = e1;
                    rs[mb][p] += e0 + e1;
                }
#pragma unroll
        for (int mb = 0; mb < 4; mb++)
#pragma unroll
            for (int p = 0; p < 2; p++) {
                rs[mb][p] += __shfl_xor_sync(0xffffffffu, rs[mb][p], 1);
                rs[mb][p] += __shfl_xor_sync(0xffffffffu, rs[mb][p], 2);
            }
        if ((lane & 3) == 0) {
#pragma unroll
            for (int mb = 0; mb < 4; mb++)
#pragma unroll
                for (int p = 0; p < 2; p++) {
                    const int row = m0 + m_w + mb * 16 + (lane >> 2) + p * 8;
                    atomicAdd(&Cf[bz * NROWS + row], rs[mb][p]);
                }
        }
#pragma unroll
        for (int mb = 0; mb < 4; mb++)
#pragma unroll
            for (int p = 0; p < 2; p++) {
                const long long row = m0 + m_w + mb * 16 + (lane >> 2) + p * 8;
#pragma unroll
                for (int nb = 0; nb < NBW; nb++) {
                    const int col = n0 + n_w + nb * 8 + (lane & 3) * 2;
                    *(unsigned*)&Ch[(long long)bz * sC + row * (long long)ldC + col] =
                        hpack(acc[mb][nb][2 * p] * mk0[nb],
                              acc[mb][nb][2 * p + 1] * mk1[nb]);
                }
            }
    }

    if (MODE == 6) {
        char* smal = smem + (int)(sa - smem_u32(smem));
        unsigned* S = (unsigned*)smal;
#pragma unroll
        for (int mb = 0; mb < 4; mb++)
#pragma unroll
            for (int p = 0; p < 2; p++) {
                const int row = m0 + m_w + mb * 16 + (lane >> 2) + p * 8;
                const float sc = 1.0f / bias[bz * NROWS + row];
                const int jl = row - m0;
#pragma unroll
                for (int nb = 0; nb < NBW; nb++) {
                    const int col = n0 + n_w + nb * 8 + (lane & 3) * 2;
                    float v0 = acc[mb][nb][2 * p] * sc;
                    float v1 = acc[mb][nb][2 * p + 1] * sc;
                    S[(col - n0) * 132 + jl] = hsplitpack(v0);
                    S[(col + 1 - n0) * 132 + jl] = hsplitpack(v1);
                }
            }
        __syncthreads();
        const int rr = m0 >> 9;
        const int j0 = m0 & 511;
        const long long ob = (long long)bz * ((long long)NROWS * CDIM) + j0;
#pragma unroll 4
        for (int rp = wid; rp < 256; rp += 8) {
            const int dl = rp >> 1;
            const int pl = rp & 1;
            uint4 q = *(uint4*)&S[dl * 132 + 4 * lane];
            unsigned a0, a1;
            if (pl == 0) {
                a0 = (q.x & 0xFFFFu) | (q.y << 16);
                a1 = (q.z & 0xFFFFu) | (q.w << 16);
            } else {
                a0 = (q.x >> 16) | (q.y & 0xFFFF0000u);
                a1 = (q.z >> 16) | (q.w & 0xFFFF0000u);
            }
            __half* dst = (pl ? Cl : Ch) + ob
                        + (long long)((((n0 + dl) << 3) + rr)) * 512;
            *(uint2*)(dst + 4 * lane) = make_uint2(a0, a1);
        }
    }
}

// ---------------------------------------------------------------------------
// Merged conversion: x, support -> (inh,inl) stacked ; Wv,Wp -> hi planes only
// ---------------------------------------------------------------------------
__global__ void __launch_bounds__(256) split_all(
    const float* __restrict__ x, const float* __restrict__ sup,
    const float* __restrict__ Wv, const float* __restrict__ Wp,
    __half* __restrict__ inh, __half* __restrict__ inl,
    __half* __restrict__ wvh, __half* __restrict__ wph)
{
    const int N1 = TOTQ * CDIM / 4;
    const int NW = CDIM * CDIM / 4;
    int i = blockIdx.x * 256 + threadIdx.x;
    if (i < 2 * N1) {
        const float* src = (i < N1) ? x : sup;
        int j = (i < N1) ? i : i - N1;
        float4 v = ((const float4*)src)[j];
        __half h0 = __float2half(v.x), h1 = __float2half(v.y);
        __half h2 = __float2half(v.z), h3 = __float2half(v.w);
        uint2 ph, pl;
        ph.x = hpack(__half2float(h0), __half2float(h1));
        ph.y = hpack(__half2float(h2), __half2float(h3));
        pl.x = hpack(v.x - __half2float(h0), v.y - __half2float(h1));
        pl.y = hpack(v.z - __half2float(h2), v.w - __half2float(h3));
        ((uint2*)inh)[i] = ph;
        ((uint2*)inl)[i] = pl;
    } else {
        int j = i - 2 * N1;
        if (j >= 2 * NW) return;
        const float* src = (j < NW) ? Wv : Wp;
        __half* dst = (j < NW) ? wvh : wph;
        int k = (j < NW) ? j : j - NW;
        float4 v = ((const float4*)src)[k];
        uint2 ph;
        ph.x = hpack(v.x, v.y);
        ph.y = hpack(v.z, v.w);
        ((uint2*)dst)[k] = ph;
    }
}

// ---------------------------------------------------------------------------
// Host: tensormap encode via driver entry point
// ---------------------------------------------------------------------------
typedef CUresult (*PFN_tmapEnc)(
    CUtensorMap*, CUtensorMapDataType, cuuint32_t, void*,
    const cuuint64_t*, const cuuint64_t*, const cuuint32_t*, const cuuint32_t*,
    CUtensorMapInterleave, CUtensorMapSwizzle, CUtensorMapL2promotion,
    CUtensorMapFloatOOBfill);

static void enc_map(PFN_tmapEnc fn, CUtensorMap* m, const void* ptr,
                    unsigned long long K, unsigned long long rows,
                    unsigned long long batches, unsigned long long ldElems,
                    unsigned long long bStrideElems, unsigned boxRows)
{
    cuuint64_t dims[3] = {K, rows, batches};
    cuuint64_t strides[2] = {ldElems * 2ull, bStrideElems * 2ull};
    cuuint32_t box[3] = {64, boxRows, 1};
    cuuint32_t estr[3] = {1, 1, 1};
    fn(m, CU_TENSOR_MAP_DATA_TYPE_FLOAT16, 3, (void*)ptr,
       dims, strides, box, estr,
       CU_TENSOR_MAP_INTERLEAVE_NONE, CU_TENSOR_MAP_SWIZZLE_128B,
       CU_TENSOR_MAP_L2_PROMOTION_L2_128B, CU_TENSOR_MAP_FLOAT_OOB_FILL_NONE);
}

extern "C" void kernel_launch(void* const* d_in, const int* in_sizes, int n_in,
                              void* d_out, int out_size)
{
    const float* x       = (const float*)d_in[0];
    const float* support = (const float*)d_in[1];
    const int*   mask    = (const int*)  d_in[2];
    const float* Wv      = (const float*)d_in[3];
    const float* Wp      = (const float*)d_in[4];
    const float* bp      = (const float*)d_in[5];
    float* out = (float*)d_out;

    float* rowsum;
    __half *inh, *inl, *wvh, *wph;
    __half *qkh, *qkl, *kth, *ah, *o2h, *o2l;
    cudaGetSymbolAddress((void**)&rowsum, g_rowsum);
    cudaGetSymbolAddress((void**)&inh, g_inh); cudaGetSymbolAddress((void**)&inl, g_inl);
    cudaGetSymbolAddress((void**)&wvh, g_wvh);
    cudaGetSymbolAddress((void**)&wph, g_wph);
    cudaGetSymbolAddress((void**)&qkh, g_qkh); cudaGetSymbolAddress((void**)&qkl, g_qkl);
    cudaGetSymbolAddress((void**)&kth, g_kth);
    cudaGetSymbolAddress((void**)&ah, g_ah);
    cudaGetSymbolAddress((void**)&o2h, g_o2h); cudaGetSymbolAddress((void**)&o2l, g_o2l);

    __half* kh = qkh + (size_t)TOTQ * CDIM;

    void* sym = nullptr;
    cudaDriverEntryPointQueryResult qres;
    cudaGetDriverEntryPointByVersion("cuTensorMapEncodeTiled", &sym, 12000,
                                     cudaEnableDefault, &qres);
    PFN_tmapEnc enc = (PFN_tmapEnc)sym;

    const long long sQK = (long long)NROWS * CDIM;
    const long long sAT = (long long)NROWS * MROWS;

    CUtensorMap tInh, tInl, tWvh, tWph;
    enc_map(enc, &tInh, inh, CDIM, 2 * TOTQ, 1, CDIM, (long long)2 * TOTQ * CDIM, 128);
    enc_map(enc, &tInl, inl, CDIM, 2 * TOTQ, 1, CDIM, (long long)2 * TOTQ * CDIM, 128);
    enc_map(enc, &tWvh, wvh, CDIM, CDIM, 1, CDIM, (long long)CDIM * CDIM, 128);
    enc_map(enc, &tWph, wph, CDIM, CDIM, 1, CDIM, (long long)CDIM * CDIM, 128);
    CUtensorMap tQh, tQl, tKh;
    enc_map(enc, &tQh, qkh, CDIM, NROWS, BB, CDIM, sQK, 128);
    enc_map(enc, &tQl, qkl, CDIM, NROWS, BB, CDIM, sQK, 128);
    enc_map(enc, &tKh, kh,  CDIM, NROWS, BB, CDIM, sQK, 128);
    CUtensorMap tAh, tKTh;
    enc_map(enc, &tAh, ah, MROWS, NROWS, BB, MROWS, sAT, 128);
    enc_map(enc, &tKTh, kth, MROWS, CDIM, BB, MROWS, (long long)CDIM * MROWS, 128);
    CUtensorMap tO2h, tO2l;
    enc_map(enc, &tO2h, o2h, CDIM, TOTQ, 1, CDIM, (long long)TOTQ * CDIM, 128);
    enc_map(enc, &tO2l, o2l, CDIM, TOTQ, 1, CDIM, (long long)TOTQ * CDIM, 128);

    // smem: proj needs max(2-stage 96K, transpose S 67.6K) ; AV 3-stage 96K
    const int SMEM_2T = 1024 + 2 * (2 * TILEA + (128 * 64 * 2));      //  99328
    const int SMEM_AV = 1024 + 3 * (TILEA + (128 * 64 * 2));          //  99328
    cudaFuncSetAttribute((const void*)tma_gemm<7,2,128,2,2>, cudaFuncAttributeMaxDynamicSharedMemorySize, SMEM_2T);
    cudaFuncSetAttribute((const void*)tma_gemm<1,2,128,2,2>, cudaFuncAttributeMaxDynamicSharedMemorySize, SMEM_2T);
    cudaFuncSetAttribute((const void*)tma_gemm<5,2,128,2,2>, cudaFuncAttributeMaxDynamicSharedMemorySize, SMEM_2T);
    cudaFuncSetAttribute((const void*)tma_gemm<6,1,128,2,3>, cudaFuncAttributeMaxDynamicSharedMemorySize, SMEM_AV);

    // 0) zero rowsum (graph-capturable)
    cudaMemsetAsync(rowsum, 0, TOTQ * sizeof(float));

    // 1) merged conversions
    {
        const int total = 2 * (TOTQ * CDIM / 4) + 2 * (CDIM * CDIM / 4);
        split_all<<<(total + 255) / 256, 256>>>(x, support, Wv, Wp,
                                                inh, inl, wvh, wph);
    }

    // 2) merged projection + fused kT transpose (MODE 7):
    //    [q;k] = [x;support] @ Wv-hi^T; q tiles write hi+lo, k tiles hi + kth
    tma_gemm<7,2,128,2,2><<<dim3(4, 256, 1), 256, SMEM_2T>>>(
        tInh, tInl, tWvh, tWvh, CDIM, CDIM, 1.0f, (long long)TOTQ,
        nullptr, nullptr, (float*)kth, qkh, qkl);

    // 3) fused QK^T + exp2 (log2e*0.125 folded) + rowsum + mask -> fp16 E
    const float QSCALE = 0.125f * 1.4426950408889634f;
    tma_gemm<5,2,128,2,2><<<dim3(32, 32, BB), 256, SMEM_2T>>>(
        tQh, tQl, tKh, tKh, MROWS, CDIM, QSCALE, sAT,
        nullptr, mask, rowsum, ah, nullptr);

    // 4) fused AV (3-stage) + per-row normalize + permute -> split-fp16 o2
    tma_gemm<6,1,128,2,3><<<dim3(4, 32, BB), 256, SMEM_AV>>>(
        tAh, tAh, tKTh, tKTh, CDIM, MROWS, 1.0f, sQK,
        rowsum, nullptr, nullptr, o2h, o2l);

    // 5) out = o2 @ Wp-hi^T + bp  (2-term, occ-2)
    tma_gemm<1,2,128,2,2><<<dim3(4, 128, 1), 256, SMEM_2T>>>(
        tO2h, tO2l, tWph, tWph, CDIM, CDIM, 1.0f, 0,
        bp, nullptr, out, nullptr, nullptr);
}